// round 13
// baseline (speedup 1.0000x reference)
#include <cuda_runtime.h>

// ---------------------------------------------------------------------------
// 2-layer LSTM (H=51), T=2048 + 16 autoregressive steps, B=512.
// R13 (= R11/R12 resubmit; both hit broker infra failures, never executed;
// same precedent as R7/R8 -> passed unchanged at R9):
// R10 pipeline + warp-aligned roles + SPLIT-PHASE NAMED BARRIERS.
//   ro0 = warps  0-6  (thr   0..223): gate1(tau) workers 0..203, x-spares 204..211
//   ro1 = warps  7-13 (thr 224..447): gate2a(tau-1) workers (Wih2 . h1),
//                                     out-dot spares 428..431, owns c2 (update2)
//   ro2 = warps 14-20 (thr 448..671): gate2b(tau-1) workers (Whh2 . h2)
// Barriers: 1 = ro0 (G1->upd1), 2 = ro1+ro2 (G2->upd2),
//           4 = ro1+ro2 (h2 publish), 3 = ro0+ro1 (h1,X publish).
// h1 triple-buffered (ro0 may run 1 tick ahead), h2/X double-buffered.
// ---------------------------------------------------------------------------

#define H     51
#define G4    204
#define T     2048
#define FUT   16
#define TT    (T + FUT)
#define NB    4
#define NBLK  128
#define WPAD  52
#define G1P   208
#define G2P   416
#define NTH   672         // 21 warps: 3 roles x 7 warps

typedef unsigned long long u64;

__device__ __forceinline__ u64 pack2(float lo, float hi) {
    u64 r; asm("mov.b64 %0, {%1,%2};" : "=l"(r) : "f"(lo), "f"(hi)); return r;
}
__device__ __forceinline__ u64 ffma2(u64 a, u64 b, u64 c) {
    u64 d; asm("fma.rn.f32x2 %0, %1, %2, %3;" : "=l"(d) : "l"(a), "l"(b), "l"(c));
    return d;
}
__device__ __forceinline__ float hsum2(u64 a) {
    float lo, hi; asm("mov.b64 {%0,%1}, %2;" : "=f"(lo), "=f"(hi) : "l"(a));
    return lo + hi;
}
__device__ __forceinline__ float sigf(float x) {
    return __fdividef(1.f, 1.f + __expf(-x));
}
__device__ __forceinline__ float tanh_fast(float x) {
    float xc = fminf(fmaxf(x, -15.f), 15.f);
    float e  = __expf(2.f * xc);
    return __fdividef(e - 1.f, e + 1.f);
}
__device__ __forceinline__ float lstm_act(float gi, float gf, float gg, float go, float& c) {
    c = sigf(gf) * c + sigf(gi) * tanh_fast(gg);
    return sigf(go) * tanh_fast(c);
}

#define BAR_A() asm volatile("bar.sync 1, 224;" ::: "memory")
#define BAR_B() asm volatile("bar.sync 2, 448;" ::: "memory")
#define BAR_C() asm volatile("bar.sync 3, 448;" ::: "memory")
#define BAR_D() asm volatile("bar.sync 4, 448;" ::: "memory")

struct __align__(16) Smem {
    float h1[3][NB][WPAD];   // triple-buffered: upd1(tau) writes slot tau%3
    float h2[2][NB][WPAD];   // upd2(tau) writes slot tau&1
    float G1[NB][G1P];
    float G2[NB][G2P];       // partials: ro1 -> col 2g, ro2 -> col 2g+1
    float WL[WPAD];
    float X[2][NB];          // dot1(tau) reads X[tau&1]
    float OUTB[NB];
    float blin;
};

// the one dot shape every worker runs: 13 float4 chunks x 4 batches
__device__ __forceinline__ void dot13(const float* __restrict__ hb,
                                      const u64* __restrict__ w, u64* acc) {
    #pragma unroll
    for (int c = 0; c < 13; c++) {
        #pragma unroll
        for (int b = 0; b < NB; b++) {
            ulonglong2 hv = *(const ulonglong2*)(hb + b * WPAD + 4 * c);
            acc[b] = ffma2(w[2 * c],     hv.x, acc[b]);
            acc[b] = ffma2(w[2 * c + 1], hv.y, acc[b]);
        }
    }
}

__global__ __launch_bounds__(NTH, 1)
void lstm_split_kernel(const float* __restrict__ input,
                       const float* __restrict__ Wih1,
                       const float* __restrict__ Whh1,
                       const float* __restrict__ bih1,
                       const float* __restrict__ bhh1,
                       const float* __restrict__ Wih2,
                       const float* __restrict__ Whh2,
                       const float* __restrict__ bih2,
                       const float* __restrict__ bhh2,
                       const float* __restrict__ Wlin,
                       const float* __restrict__ blin,
                       float* __restrict__ out)
{
    __shared__ Smem s;
    const int j   = threadIdx.x;
    const int bb0 = blockIdx.x * NB;

    const int  g    = j / 224;            // role (warp-uniform, 224 = 7 warps)
    const int  wr   = j - g * 224;
    const bool work = (wr < G4);
    const int  row  = wr;
    const bool isX   = (g == 0 && wr >= 204 && wr < 208);
    const bool isOut = (g == 1 && wr >= 204 && wr < 208);

    // ---------------- prologue: one weight row per worker ----------------
    u64 wreg[26];
    float bj = 0.f, wi1 = 0.f;
    if (work) {
        const float* wsrc = (g == 0) ? (Whh1 + row * H)
                          : (g == 1) ? (Wih2 + row * H)
                                     : (Whh2 + row * H);
        #pragma unroll
        for (int p = 0; p < 26; p++) {
            int k1 = 2 * p + 1;
            wreg[p] = pack2(wsrc[2 * p], (k1 < H) ? wsrc[k1] : 0.f);
        }
        if (g == 0) { bj = bih1[row] + bhh1[row]; wi1 = Wih1[row]; }
        if (g == 1) { bj = bih2[row] + bhh2[row]; }
    }
    const int b1 = work ? (row / H) : 0;
    const int u1 = work ? (row % H) : 0;
    float cc = 0.f;                       // c1 for g0 workers, c2 for g1 workers

    // init shared state
    for (int idx = j; idx < 3 * NB * WPAD; idx += NTH) (&s.h1[0][0][0])[idx] = 0.f;
    for (int idx = j; idx < 2 * NB * WPAD; idx += NTH) (&s.h2[0][0][0])[idx] = 0.f;
    if (j < WPAD) s.WL[j] = (j < H) ? Wlin[j] : 0.f;
    if (j < NB) {
        s.X[0][j]  = input[(size_t)(bb0 + j) * T];
        s.X[1][j]  = 0.f;
        s.OUTB[j]  = 0.f;
    }
    if (j == 0) s.blin = blin[0];
    __syncthreads();

    // --------------------------- pipelined main loop ---------------------------
    for (int tau = 0; tau <= T + 1; tau++) {
        const int s1r = (tau + 2) % 3;    // h1 state (tau-1)
        const int s1w = tau % 3;          // h1 state (tau)
        const int s2r = (tau + 1) & 1;    // h2 state (tau-2)
        const int s2w = tau & 1;          // h2 state (tau-1)

        if (g == 0) {
            float xr = 0.f;
            if (work && tau < T) {                       // gate1(tau)
                u64 acc[NB];
                #pragma unroll
                for (int b = 0; b < NB; b++)
                    acc[b] = pack2(fmaf(wi1, s.X[tau & 1][b], bj), 0.f);
                dot13(&s.h1[s1r][0][0], wreg, acc);
                #pragma unroll
                for (int b = 0; b < NB; b++) s.G1[b][row] = hsum2(acc[b]);
            }
            if (isX && tau <= T - 2)
                xr = input[(size_t)(bb0 + (wr - 204)) * T + (tau + 1)];
            BAR_A();                                     // G1 visible within ro0
            if (work && tau < T) {                       // update1 -> h1(tau)
                float gi = s.G1[b1][u1],         gf = s.G1[b1][H + u1];
                float gg = s.G1[b1][2 * H + u1], go = s.G1[b1][3 * H + u1];
                s.h1[s1w][b1][u1] = lstm_act(gi, gf, gg, go, cc);
            }
            if (isX && tau <= T - 2) s.X[(tau + 1) & 1][wr - 204] = xr;
            BAR_C();                                     // h1,X published to ro1/ro0
        } else if (g == 1) {
            const bool act = (tau >= 1 && tau <= T);
            if (work && act) {                           // gate2a(tau-1): Wih2 . h1
                u64 acc[NB];
                #pragma unroll
                for (int b = 0; b < NB; b++) acc[b] = pack2(bj, 0.f);
                dot13(&s.h1[s1r][0][0], wreg, acc);
                #pragma unroll
                for (int b = 0; b < NB; b++) s.G2[b][2 * row] = hsum2(acc[b]);
            }
            if (isOut && tau >= 2) {                     // out(tau-2) from h2(tau-2)
                const int b = wr - 204;
                float a0 = 0.f, a1 = 0.f, a2 = 0.f, a3 = 0.f;
                const float* h2p = &s.h2[s2r][b][0];
                #pragma unroll
                for (int p = 0; p < 13; p++) {
                    float4 w = *(const float4*)&s.WL[4 * p];
                    float4 h = *(const float4*)&h2p[4 * p];
                    a0 = fmaf(w.x, h.x, a0);  a1 = fmaf(w.y, h.y, a1);
                    a2 = fmaf(w.z, h.z, a2);  a3 = fmaf(w.w, h.w, a3);
                }
                float val = (a0 + a1) + (a2 + a3) + s.blin;
                out[(size_t)(bb0 + b) * TT + (tau - 2)] = val;
                s.OUTB[b] = val;
            }
            BAR_B();                                     // G2a+G2b visible
            if (work && act) {                           // update2 -> h2(tau-1)
                float2 vi = *(const float2*)&s.G2[b1][2 * u1];
                float2 vf = *(const float2*)&s.G2[b1][2 * (H + u1)];
                float2 vg = *(const float2*)&s.G2[b1][2 * (2 * H + u1)];
                float2 vo = *(const float2*)&s.G2[b1][2 * (3 * H + u1)];
                s.h2[s2w][b1][u1] = lstm_act(vi.x + vi.y, vf.x + vf.y,
                                             vg.x + vg.y, vo.x + vo.y, cc);
            }
            BAR_D();                                     // h2 published to ro2
            BAR_C();                                     // join h1/X rendezvous
        } else {
            const bool act = (tau >= 1 && tau <= T);
            if (work && act) {                           // gate2b(tau-1): Whh2 . h2
                u64 acc[NB];
                #pragma unroll
                for (int b = 0; b < NB; b++) acc[b] = pack2(0.f, 0.f);
                dot13(&s.h2[s2r][0][0], wreg, acc);
                #pragma unroll
                for (int b = 0; b < NB; b++) s.G2[b][2 * row + 1] = hsum2(acc[b]);
            }
            BAR_B();
            BAR_D();
        }
    }
    __syncthreads();

    // --------------------- serial autoregressive epilogue ---------------------
    for (int t = T; t < TT; t++) {
        const int e1r = (t + 2) % 3, e1w = t % 3;
        const int e2r = t & 1,       e2w = (t + 1) & 1;

        if (g == 0 && work) {                    // gate1(t), x = out(t-1)
            u64 acc[NB];
            #pragma unroll
            for (int b = 0; b < NB; b++)
                acc[b] = pack2(fmaf(wi1, s.OUTB[b], bj), 0.f);
            dot13(&s.h1[e1r][0][0], wreg, acc);
            #pragma unroll
            for (int b = 0; b < NB; b++) s.G1[b][row] = hsum2(acc[b]);
        }
        __syncthreads();
        if (g == 0 && work) {                    // update1 -> h1(t)
            float gi = s.G1[b1][u1],         gf = s.G1[b1][H + u1];
            float gg = s.G1[b1][2 * H + u1], go = s.G1[b1][3 * H + u1];
            s.h1[e1w][b1][u1] = lstm_act(gi, gf, gg, go, cc);
        }
        __syncthreads();
        if (g == 1 && work) {                    // gate2a(t): Wih2 . h1(t)
            u64 acc[NB];
            #pragma unroll
            for (int b = 0; b < NB; b++) acc[b] = pack2(bj, 0.f);
            dot13(&s.h1[e1w][0][0], wreg, acc);
            #pragma unroll
            for (int b = 0; b < NB; b++) s.G2[b][2 * row] = hsum2(acc[b]);
        }
        if (g == 2 && work) {                    // gate2b(t): Whh2 . h2(t-1)
            u64 acc[NB];
            #pragma unroll
            for (int b = 0; b < NB; b++) acc[b] = pack2(0.f, 0.f);
            dot13(&s.h2[e2r][0][0], wreg, acc);
            #pragma unroll
            for (int b = 0; b < NB; b++) s.G2[b][2 * row + 1] = hsum2(acc[b]);
        }
        __syncthreads();
        if (g == 1 && work) {                    // update2 -> h2(t)
            float2 vi = *(const float2*)&s.G2[b1][2 * u1];
            float2 vf = *(const float2*)&s.G2[b1][2 * (H + u1)];
            float2 vg = *(const float2*)&s.G2[b1][2 * (2 * H + u1)];
            float2 vo = *(const float2*)&s.G2[b1][2 * (3 * H + u1)];
            s.h2[e2w][b1][u1] = lstm_act(vi.x + vi.y, vf.x + vf.y,
                                         vg.x + vg.y, vo.x + vo.y, cc);
        }
        __syncthreads();
        if (isOut) {                             // out(t) from h2(t)
            const int b = wr - 204;
            float a0 = 0.f, a1 = 0.f, a2 = 0.f, a3 = 0.f;
            const float* h2p = &s.h2[e2w][b][0];
            #pragma unroll
            for (int p = 0; p < 13; p++) {
                float4 w = *(const float4*)&s.WL[4 * p];
                float4 h = *(const float4*)&h2p[4 * p];
                a0 = fmaf(w.x, h.x, a0);  a1 = fmaf(w.y, h.y, a1);
                a2 = fmaf(w.z, h.z, a2);  a3 = fmaf(w.w, h.w, a3);
            }
            float val = (a0 + a1) + (a2 + a3) + s.blin;
            out[(size_t)(bb0 + b) * TT + t] = val;
            s.OUTB[b] = val;
        }
        __syncthreads();
    }
}

extern "C" void kernel_launch(void* const* d_in, const int* in_sizes, int n_in,
                              void* d_out, int out_size)
{
    const float* input = (const float*)d_in[0];
    const float* Wih1  = (const float*)d_in[1];
    const float* Whh1  = (const float*)d_in[2];
    const float* bih1  = (const float*)d_in[3];
    const float* bhh1  = (const float*)d_in[4];
    const float* Wih2  = (const float*)d_in[5];
    const float* Whh2  = (const float*)d_in[6];
    const float* bih2  = (const float*)d_in[7];
    const float* bhh2  = (const float*)d_in[8];
    const float* Wlin  = (const float*)d_in[9];
    const float* blin  = (const float*)d_in[10];
    float* out = (float*)d_out;

    lstm_split_kernel<<<NBLK, NTH>>>(
        input, Wih1, Whh1, bih1, bhh1, Wih2, Whh2, bih2, bhh2, Wlin, blin, out);
}

// round 14
// speedup vs baseline: 1.0012x; 1.0012x over previous
#include <cuda_runtime.h>

// ---------------------------------------------------------------------------
// 2-layer LSTM (H=51), T=2048 + 16 autoregressive steps, B=512.
// R14: gate smem round trip ELIMINATED via intra-warp shfl transposes.
//   ro0 (thr 0..223):  layer-1. worker j<204: unit u=j>>2, gate g=j&3
//                      -> 4 gates of u in one lane-quad. After dot, 4-shfl
//                      butterfly transposes (gate x batch) -> lane owns one
//                      batch's 4 gates -> activation inline, no barrier.
//                      spares: 204..207 out-dot(tau-2), 208..211 x-prefetch.
//   ro1 (thr 224..639): layer-2. lane = 8*(u%4) + 2*g + m;
//                      m=0: Wih2 row . h1,  m=1: Whh2 row . h2.
//                      shfl.xor(1) sums partials, butterfly (2,4) transposes,
//                      m=0 lane does activation + h2 store.
// ONE __syncthreads per tick (publishes h1/h2/X). Weights: 26 u64/thread.
// h1/h2/X double-buffered by step parity: state(s) lives in slot s&1.
// ---------------------------------------------------------------------------

#define H     51
#define T     2048
#define FUT   16
#define TT    (T + FUT)
#define NB    4
#define NBLK  128
#define WPAD  52          // h row pitch; col 51 stays 0
#define NTH   640         // ro0: 7 warps, ro1: 13 warps

typedef unsigned long long u64;

__device__ __forceinline__ u64 pack2(float lo, float hi) {
    u64 r; asm("mov.b64 %0, {%1,%2};" : "=l"(r) : "f"(lo), "f"(hi)); return r;
}
__device__ __forceinline__ u64 ffma2(u64 a, u64 b, u64 c) {
    u64 d; asm("fma.rn.f32x2 %0, %1, %2, %3;" : "=l"(d) : "l"(a), "l"(b), "l"(c));
    return d;
}
__device__ __forceinline__ float hsum2(u64 a) {
    float lo, hi; asm("mov.b64 {%0,%1}, %2;" : "=f"(lo), "=f"(hi) : "l"(a));
    return lo + hi;
}
__device__ __forceinline__ float sigf(float x) {
    return __fdividef(1.f, 1.f + __expf(-x));
}
__device__ __forceinline__ float tanh_fast(float x) {
    float xc = fminf(fmaxf(x, -15.f), 15.f);
    float e  = __expf(2.f * xc);
    return __fdividef(e - 1.f, e + 1.f);
}
__device__ __forceinline__ float lstm_act(float gi, float gf, float gg, float go, float& c) {
    c = sigf(gf) * c + sigf(gi) * tanh_fast(gg);
    return sigf(go) * tanh_fast(c);
}

// xor-butterfly 4x4 transpose: lane (virtual id by bits x1,x2) holds v[0..3]
// = M[vlane][0..3]; after call holds M[0..3][vlane].
__device__ __forceinline__ void bfly_transpose(float v[4], unsigned mask,
                                               int x1, int x2, bool b1, bool b2) {
    float s;
    s = b1 ? v[0] : v[1]; s = __shfl_xor_sync(mask, s, x1); if (b1) v[0] = s; else v[1] = s;
    s = b1 ? v[2] : v[3]; s = __shfl_xor_sync(mask, s, x1); if (b1) v[2] = s; else v[3] = s;
    s = b2 ? v[0] : v[2]; s = __shfl_xor_sync(mask, s, x2); if (b2) v[0] = s; else v[2] = s;
    s = b2 ? v[1] : v[3]; s = __shfl_xor_sync(mask, s, x2); if (b2) v[1] = s; else v[3] = s;
}

struct __align__(16) Smem {
    float h1[2][NB][WPAD];   // state(s) in slot s&1; col 51 = 0
    float h2[2][NB][WPAD];
    float WL[WPAD];
    float X[2][NB];          // x(s) in slot s&1
    float OUTB[NB];
    float blin;
};

__device__ __forceinline__ void dot13(const float* __restrict__ hb,
                                      const u64* __restrict__ w, u64* acc) {
    #pragma unroll
    for (int c = 0; c < 13; c++) {
        #pragma unroll
        for (int b = 0; b < NB; b++) {
            ulonglong2 hv = *(const ulonglong2*)(hb + b * WPAD + 4 * c);
            acc[b] = ffma2(w[2 * c],     hv.x, acc[b]);
            acc[b] = ffma2(w[2 * c + 1], hv.y, acc[b]);
        }
    }
}

__global__ __launch_bounds__(NTH, 1)
void lstm_fused_kernel(const float* __restrict__ input,
                       const float* __restrict__ Wih1,
                       const float* __restrict__ Whh1,
                       const float* __restrict__ bih1,
                       const float* __restrict__ bhh1,
                       const float* __restrict__ Wih2,
                       const float* __restrict__ Whh2,
                       const float* __restrict__ bih2,
                       const float* __restrict__ bhh2,
                       const float* __restrict__ Wlin,
                       const float* __restrict__ blin,
                       float* __restrict__ out)
{
    __shared__ Smem s;
    const int j    = threadIdx.x;
    const int lane = j & 31;
    const int bb0  = blockIdx.x * NB;

    const bool r0 = (j < 224);
    int u, g, m; bool work;
    if (r0) {
        u = j >> 2;  g = j & 3;  m = 0;
        work = (j < 204);
    } else {
        int w2 = (j - 224) >> 5;          // ro1 warp index 0..12
        u = 4 * w2 + (lane >> 3);
        g = (lane >> 1) & 3;
        m = lane & 1;
        work = (u < H);
    }
    const bool isOut = (j >= 204 && j < 208);
    const bool isX   = (j >= 208 && j < 212);

    // ---------------- prologue: one half/full weight row per worker ----------
    u64 wreg[26];
    float bj = 0.f, wi1 = 0.f;
    if (work) {
        const int row = g * H + u;
        const float* wsrc = r0 ? (Whh1 + row * H)
                               : (m == 0 ? (Wih2 + row * H) : (Whh2 + row * H));
        #pragma unroll
        for (int p = 0; p < 26; p++) {
            int k1 = 2 * p + 1;
            wreg[p] = pack2(wsrc[2 * p], (k1 < H) ? wsrc[k1] : 0.f);
        }
        if (r0)          { bj = bih1[row] + bhh1[row]; wi1 = Wih1[row]; }
        else if (m == 0) { bj = bih2[row] + bhh2[row]; }
    }
    float cc = 0.f;                      // c1 for ro0 workers, c2 for ro1 m=0

    // init shared state
    for (int idx = j; idx < 2 * NB * WPAD; idx += NTH) {
        (&s.h1[0][0][0])[idx] = 0.f;
        (&s.h2[0][0][0])[idx] = 0.f;
    }
    if (j < WPAD) s.WL[j] = (j < H) ? Wlin[j] : 0.f;
    if (j < NB) {
        s.X[0][j]  = input[(size_t)(bb0 + j) * T];
        s.X[1][j]  = 0.f;
        s.OUTB[j]  = 0.f;
    }
    if (j == 0) s.blin = blin[0];
    __syncthreads();

    // --------------------------- main loop: 1 barrier/tick ---------------------------
    for (int tau = 0; tau <= T + 1; tau++) {
        const int sA = tau & 1, sB = sA ^ 1;   // sB == (tau-1)&1 == (tau+1)&1

        if (r0) {
            if (work && tau < T) {             // gate1(tau) + update1(tau), fused
                u64 acc[NB];
                #pragma unroll
                for (int b = 0; b < NB; b++)
                    acc[b] = pack2(fmaf(wi1, s.X[sA][b], bj), 0.f);
                dot13(&s.h1[sB][0][0], wreg, acc);       // h1(tau-1)
                float v[4];
                #pragma unroll
                for (int b = 0; b < NB; b++) v[b] = hsum2(acc[b]);
                unsigned qm = 0xFu << (lane & ~3);
                bfly_transpose(v, qm, 1, 2, (lane & 1) != 0, (lane & 2) != 0);
                // lane (quad pos p) now holds (i,f,g,o) of batch p for unit u
                float h = lstm_act(v[0], v[1], v[2], v[3], cc);
                s.h1[sA][lane & 3][u] = h;               // h1(tau)
            }
            if (isOut && tau >= 2) {           // out(tau-2) from h2(tau-2)=slot sA
                const int b = j - 204;
                float a0 = 0.f, a1 = 0.f, a2 = 0.f, a3 = 0.f;
                const float* h2p = &s.h2[sA][b][0];
                #pragma unroll
                for (int p = 0; p < 13; p++) {
                    float4 w = *(const float4*)&s.WL[4 * p];
                    float4 h = *(const float4*)&h2p[4 * p];
                    a0 = fmaf(w.x, h.x, a0);  a1 = fmaf(w.y, h.y, a1);
                    a2 = fmaf(w.z, h.z, a2);  a3 = fmaf(w.w, h.w, a3);
                }
                float val = (a0 + a1) + (a2 + a3) + s.blin;
                out[(size_t)(bb0 + b) * TT + (tau - 2)] = val;
                s.OUTB[b] = val;
            }
            if (isX && tau <= T - 2)           // x(tau+1) -> slot sB
                s.X[sB][j - 208] = input[(size_t)(bb0 + (j - 208)) * T + (tau + 1)];
        } else {
            if (work && tau >= 1 && tau <= T) {    // gate2(tau-1) + update2(tau-1)
                u64 acc[NB];
                #pragma unroll
                for (int b = 0; b < NB; b++) acc[b] = pack2(bj, 0.f);  // bj=0 for m=1
                const float* hb = (m == 0) ? &s.h1[sB][0][0]   // h1(tau-1)
                                           : &s.h2[sA][0][0];  // h2(tau-2)
                dot13(hb, wreg, acc);
                float v[4];
                #pragma unroll
                for (int b = 0; b < NB; b++) v[b] = hsum2(acc[b]);
                unsigned gm = 0xFFu << (lane & ~7);
                #pragma unroll
                for (int b = 0; b < NB; b++)           // sum the two matrix halves
                    v[b] += __shfl_xor_sync(gm, v[b], 1);
                bfly_transpose(v, gm, 2, 4, (lane & 2) != 0, (lane & 4) != 0);
                if (m == 0) {                          // lane 2p owns batch p
                    float h = lstm_act(v[0], v[1], v[2], v[3], cc);
                    s.h2[sB][(lane >> 1) & 3][u] = h;  // h2(tau-1)
                }
            }
        }
        __syncthreads();                   // publish h1(tau), h2(tau-1), X(tau+1)
    }

    // --------------------- serial autoregressive epilogue ---------------------
    for (int t = T; t < TT; t++) {
        const int sW = t & 1, sR = sW ^ 1;

        if (r0 && work) {                  // gate1(t) with x = out(t-1) + update1
            u64 acc[NB];
            #pragma unroll
            for (int b = 0; b < NB; b++)
                acc[b] = pack2(fmaf(wi1, s.OUTB[b], bj), 0.f);
            dot13(&s.h1[sR][0][0], wreg, acc);
            float v[4];
            #pragma unroll
            for (int b = 0; b < NB; b++) v[b] = hsum2(acc[b]);
            unsigned qm = 0xFu << (lane & ~3);
            bfly_transpose(v, qm, 1, 2, (lane & 1) != 0, (lane & 2) != 0);
            float h = lstm_act(v[0], v[1], v[2], v[3], cc);
            s.h1[sW][lane & 3][u] = h;
        }
        __syncthreads();
        if (!r0 && work) {                 // gate2(t) + update2(t)
            u64 acc[NB];
            #pragma unroll
            for (int b = 0; b < NB; b++) acc[b] = pack2(bj, 0.f);
            const float* hb = (m == 0) ? &s.h1[sW][0][0]   // h1(t)
                                       : &s.h2[sR][0][0];  // h2(t-1)
            dot13(hb, wreg, acc);
            float v[4];
            #pragma unroll
            for (int b = 0; b < NB; b++) v[b] = hsum2(acc[b]);
            unsigned gm = 0xFFu << (lane & ~7);
            #pragma unroll
            for (int b = 0; b < NB; b++)
                v[b] += __shfl_xor_sync(gm, v[b], 1);
            bfly_transpose(v, gm, 2, 4, (lane & 2) != 0, (lane & 4) != 0);
            if (m == 0) {
                float h = lstm_act(v[0], v[1], v[2], v[3], cc);
                s.h2[sW][(lane >> 1) & 3][u] = h;
            }
        }
        __syncthreads();
        if (isOut) {                       // out(t) from h2(t)
            const int b = j - 204;
            float a0 = 0.f, a1 = 0.f, a2 = 0.f, a3 = 0.f;
            const float* h2p = &s.h2[sW][b][0];
            #pragma unroll
            for (int p = 0; p < 13; p++) {
                float4 w = *(const float4*)&s.WL[4 * p];
                float4 h = *(const float4*)&h2p[4 * p];
                a0 = fmaf(w.x, h.x, a0);  a1 = fmaf(w.y, h.y, a1);
                a2 = fmaf(w.z, h.z, a2);  a3 = fmaf(w.w, h.w, a3);
            }
            float val = (a0 + a1) + (a2 + a3) + s.blin;
            out[(size_t)(bb0 + b) * TT + t] = val;
            s.OUTB[b] = val;
        }
        __syncthreads();
    }
}

extern "C" void kernel_launch(void* const* d_in, const int* in_sizes, int n_in,
                              void* d_out, int out_size)
{
    const float* input = (const float*)d_in[0];
    const float* Wih1  = (const float*)d_in[1];
    const float* Whh1  = (const float*)d_in[2];
    const float* bih1  = (const float*)d_in[3];
    const float* bhh1  = (const float*)d_in[4];
    const float* Wih2  = (const float*)d_in[5];
    const float* Whh2  = (const float*)d_in[6];
    const float* bih2  = (const float*)d_in[7];
    const float* bhh2  = (const float*)d_in[8];
    const float* Wlin  = (const float*)d_in[9];
    const float* blin  = (const float*)d_in[10];
    float* out = (float*)d_out;

    lstm_fused_kernel<<<NBLK, NTH>>>(
        input, Wih1, Whh1, bih1, bhh1, Wih2, Whh2, bih2, bhh2, Wlin, blin, out);
}

// round 16
// speedup vs baseline: 1.0343x; 1.0330x over previous
#include <cuda_runtime.h>

// ---------------------------------------------------------------------------
// 2-layer LSTM (H=51), T=2048 + 16 autoregressive steps, B=512.
// R16 (= R15 resubmit after broker infra failure; + fix: zero ring pad col
// once in prologue so the post-pass float4 reads never touch uninit memory):
// R10 pipeline, warp-aligned roles, out-dot removed from the tick via a
// GMEM h2 ring + parallel post-pass.
// Roles:
//   ro0 = warps  0-6  (thr   0..223): gate1(tau) workers 0..203, x 204..207,
//                                     owns c1 (update1)
//   ro1 = warps  7-13 (thr 224..447): gate2a(tau-1) = b2 + Wih2 . h1(tau-1),
//                                     owns c2 (update2) + ring STG
//   ro2 = warps 14-20 (thr 448..671): gate2b(tau-1) = Whh2 . h2(tau-2)
// Weights: 26 f32x2 regs/thread. h1/h2/X double-buffered by parity.
// Epilogue: 16 serial autoregressive steps (out feedback), then ring->out pass.
// ---------------------------------------------------------------------------

#define H     51
#define G4    204
#define T     2048
#define FUT   16
#define TT    (T + FUT)
#define NB    4
#define NBLK  128
#define WPAD  52          // padded row pitch (floats; col 51 = 0)
#define G1P   208
#define G2P   416
#define NTH   672         // 21 warps: 3 roles x 7 warps

typedef unsigned long long u64;

// h2 history ring: [block][t][batch][u(padded)]  = 218 MB device global
__device__ float g_ring[NBLK][T][NB][WPAD];

__device__ __forceinline__ u64 pack2(float lo, float hi) {
    u64 r; asm("mov.b64 %0, {%1,%2};" : "=l"(r) : "f"(lo), "f"(hi)); return r;
}
__device__ __forceinline__ u64 ffma2(u64 a, u64 b, u64 c) {
    u64 d; asm("fma.rn.f32x2 %0, %1, %2, %3;" : "=l"(d) : "l"(a), "l"(b), "l"(c));
    return d;
}
__device__ __forceinline__ float hsum2(u64 a) {
    float lo, hi; asm("mov.b64 {%0,%1}, %2;" : "=f"(lo), "=f"(hi) : "l"(a));
    return lo + hi;
}
__device__ __forceinline__ float sigf(float x) {
    return __fdividef(1.f, 1.f + __expf(-x));
}
__device__ __forceinline__ float tanh_fast(float x) {
    float xc = fminf(fmaxf(x, -15.f), 15.f);
    float e  = __expf(2.f * xc);
    return __fdividef(e - 1.f, e + 1.f);
}
__device__ __forceinline__ float lstm_act(float gi, float gf, float gg, float go, float& c) {
    c = sigf(gf) * c + sigf(gi) * tanh_fast(gg);
    return sigf(go) * tanh_fast(c);
}

struct __align__(16) Smem {
    float h1[2][NB][WPAD];   // h1(s) in slot s&1
    float h2[2][NB][WPAD];   // h2(s) in slot s&1
    float G1[NB][G1P];
    float G2[NB][G2P];       // partials: ro1 -> col 2g, ro2 -> col 2g+1
    float WL[WPAD];
    float X[2][NB];          // x(s) in slot s&1
    float OUTB[NB];
    float blin;
};

__device__ __forceinline__ void dot13(const float* __restrict__ hb,
                                      const u64* __restrict__ w, u64* acc) {
    #pragma unroll
    for (int c = 0; c < 13; c++) {
        #pragma unroll
        for (int b = 0; b < NB; b++) {
            ulonglong2 hv = *(const ulonglong2*)(hb + b * WPAD + 4 * c);
            acc[b] = ffma2(w[2 * c],     hv.x, acc[b]);
            acc[b] = ffma2(w[2 * c + 1], hv.y, acc[b]);
        }
    }
}

__global__ __launch_bounds__(NTH, 1)
void lstm_ring_kernel(const float* __restrict__ input,
                      const float* __restrict__ Wih1,
                      const float* __restrict__ Whh1,
                      const float* __restrict__ bih1,
                      const float* __restrict__ bhh1,
                      const float* __restrict__ Wih2,
                      const float* __restrict__ Whh2,
                      const float* __restrict__ bih2,
                      const float* __restrict__ bhh2,
                      const float* __restrict__ Wlin,
                      const float* __restrict__ blin,
                      float* __restrict__ out)
{
    __shared__ Smem s;
    const int j   = threadIdx.x;
    const int blk = blockIdx.x;
    const int bb0 = blk * NB;

    const int  g    = j / 224;            // role, warp-uniform
    const int  wr   = j - g * 224;
    const bool work = (wr < G4);
    const int  row  = wr;
    const bool svc  = (g == 0 && wr >= 204 && wr < 208);   // x-prefetch / epi-out

    // ---------------- prologue: one weight row per worker ----------------
    u64 wreg[26];
    float bj = 0.f, wi1 = 0.f;
    if (work) {
        const float* wsrc = (g == 0) ? (Whh1 + row * H)
                          : (g == 1) ? (Wih2 + row * H)
                                     : (Whh2 + row * H);
        #pragma unroll
        for (int p = 0; p < 26; p++) {
            int k1 = 2 * p + 1;
            wreg[p] = pack2(wsrc[2 * p], (k1 < H) ? wsrc[k1] : 0.f);
        }
        if (g == 0) { bj = bih1[row] + bhh1[row]; wi1 = Wih1[row]; }
        if (g == 1) { bj = bih2[row] + bhh2[row]; }
    }
    const int b1 = work ? (row / H) : 0;
    const int u1 = work ? (row % H) : 0;
    float cc = 0.f;                       // c1 for g0 workers, c2 for g1 workers

    // init shared state + ring pad column (col 51 is read by the post-pass
    // float4 loads but never written by update2 -> zero it once here)
    for (int idx = j; idx < 2 * NB * WPAD; idx += NTH) {
        (&s.h1[0][0][0])[idx] = 0.f;
        (&s.h2[0][0][0])[idx] = 0.f;
    }
    for (int idx = j; idx < T * NB; idx += NTH)
        g_ring[blk][idx >> 2][idx & 3][H] = 0.f;
    if (j < WPAD) s.WL[j] = (j < H) ? Wlin[j] : 0.f;
    if (j < NB) {
        s.X[0][j]  = input[(size_t)(bb0 + j) * T];
        s.X[1][j]  = 0.f;
        s.OUTB[j]  = 0.f;
    }
    if (j == 0) s.blin = blin[0];
    __syncthreads();

    // --------------------------- pipelined main loop ---------------------------
    for (int tau = 0; tau <= T; tau++) {
        const int pA = tau & 1, pB = pA ^ 1;
        const bool l1act = (tau < T);
        const bool l2act = (tau >= 1);
        float xr = 0.f;

        // ================= dot phase =================
        if (work) {
            if (g == 0) {
                if (l1act) {                                 // gate1(tau)
                    u64 acc[NB];
                    #pragma unroll
                    for (int b = 0; b < NB; b++)
                        acc[b] = pack2(fmaf(wi1, s.X[pA][b], bj), 0.f);
                    dot13(&s.h1[pB][0][0], wreg, acc);       // h1(tau-1)
                    #pragma unroll
                    for (int b = 0; b < NB; b++) s.G1[b][row] = hsum2(acc[b]);
                }
            } else if (g == 1) {
                if (l2act) {                                 // gate2a(tau-1)
                    u64 acc[NB];
                    #pragma unroll
                    for (int b = 0; b < NB; b++) acc[b] = pack2(bj, 0.f);
                    dot13(&s.h1[pB][0][0], wreg, acc);       // h1(tau-1)
                    #pragma unroll
                    for (int b = 0; b < NB; b++) s.G2[b][2 * row] = hsum2(acc[b]);
                }
            } else {
                if (l2act) {                                 // gate2b(tau-1)
                    u64 acc[NB];
                    #pragma unroll
                    for (int b = 0; b < NB; b++) acc[b] = pack2(0.f, 0.f);
                    dot13(&s.h2[pA][0][0], wreg, acc);       // h2(tau-2)
                    #pragma unroll
                    for (int b = 0; b < NB; b++) s.G2[b][2 * row + 1] = hsum2(acc[b]);
                }
            }
        }
        if (svc && tau <= T - 2)
            xr = input[(size_t)(bb0 + (wr - 204)) * T + (tau + 1)];
        __syncthreads();                                     // S1: G1, G2 visible

        // ================= update phase =================
        if (work && g == 0 && l1act) {                       // update1 -> h1(tau)
            float gi = s.G1[b1][u1],         gf = s.G1[b1][H + u1];
            float gg = s.G1[b1][2 * H + u1], go = s.G1[b1][3 * H + u1];
            s.h1[pA][b1][u1] = lstm_act(gi, gf, gg, go, cc);
        }
        if (work && g == 1 && l2act) {                       // update2 -> h2(tau-1)
            float2 vi = *(const float2*)&s.G2[b1][2 * u1];
            float2 vf = *(const float2*)&s.G2[b1][2 * (H + u1)];
            float2 vg = *(const float2*)&s.G2[b1][2 * (2 * H + u1)];
            float2 vo = *(const float2*)&s.G2[b1][2 * (3 * H + u1)];
            float h = lstm_act(vi.x + vi.y, vf.x + vf.y,
                               vg.x + vg.y, vo.x + vo.y, cc);
            s.h2[pB][b1][u1] = h;
            g_ring[blk][tau - 1][b1][u1] = h;                // stream h2(tau-1)
        }
        if (svc && tau <= T - 2) s.X[pB][wr - 204] = xr;
        __syncthreads();                                     // S2: h1, h2, X visible
    }

    // --------------------- serial autoregressive epilogue ---------------------
    // Entry: h1(T-1) in slot (T-1)&1, h2(T-1) in slot (T-1)&1, c-states live.
    for (int t = T; t < TT; t++) {
        const int sW = t & 1, sR = sW ^ 1;

        if (svc) {                               // out(t-1) from h2(t-1) -> OUTB
            const int b = wr - 204;
            float a0 = 0.f, a1 = 0.f, a2 = 0.f, a3 = 0.f;
            const float* h2p = &s.h2[sR][b][0];
            #pragma unroll
            for (int p = 0; p < 13; p++) {
                float4 w = *(const float4*)&s.WL[4 * p];
                float4 h = *(const float4*)&h2p[4 * p];
                a0 = fmaf(w.x, h.x, a0);  a1 = fmaf(w.y, h.y, a1);
                a2 = fmaf(w.z, h.z, a2);  a3 = fmaf(w.w, h.w, a3);
            }
            float val = (a0 + a1) + (a2 + a3) + s.blin;
            out[(size_t)(bb0 + b) * TT + (t - 1)] = val;
            s.OUTB[b] = val;
        }
        __syncthreads();
        if (g == 0 && work) {                    // gate1(t), x = out(t-1)
            u64 acc[NB];
            #pragma unroll
            for (int b = 0; b < NB; b++)
                acc[b] = pack2(fmaf(wi1, s.OUTB[b], bj), 0.f);
            dot13(&s.h1[sR][0][0], wreg, acc);
            #pragma unroll
            for (int b = 0; b < NB; b++) s.G1[b][row] = hsum2(acc[b]);
        }
        __syncthreads();
        if (g == 0 && work) {                    // update1 -> h1(t)
            float gi = s.G1[b1][u1],         gf = s.G1[b1][H + u1];
            float gg = s.G1[b1][2 * H + u1], go = s.G1[b1][3 * H + u1];
            s.h1[sW][b1][u1] = lstm_act(gi, gf, gg, go, cc);
        }
        __syncthreads();
        if (g == 1 && work) {                    // gate2a(t): Wih2 . h1(t)
            u64 acc[NB];
            #pragma unroll
            for (int b = 0; b < NB; b++) acc[b] = pack2(bj, 0.f);
            dot13(&s.h1[sW][0][0], wreg, acc);
            #pragma unroll
            for (int b = 0; b < NB; b++) s.G2[b][2 * row] = hsum2(acc[b]);
        }
        if (g == 2 && work) {                    // gate2b(t): Whh2 . h2(t-1)
            u64 acc[NB];
            #pragma unroll
            for (int b = 0; b < NB; b++) acc[b] = pack2(0.f, 0.f);
            dot13(&s.h2[sR][0][0], wreg, acc);
            #pragma unroll
            for (int b = 0; b < NB; b++) s.G2[b][2 * row + 1] = hsum2(acc[b]);
        }
        __syncthreads();
        if (g == 1 && work) {                    // update2 -> h2(t)
            float2 vi = *(const float2*)&s.G2[b1][2 * u1];
            float2 vf = *(const float2*)&s.G2[b1][2 * (H + u1)];
            float2 vg = *(const float2*)&s.G2[b1][2 * (2 * H + u1)];
            float2 vo = *(const float2*)&s.G2[b1][2 * (3 * H + u1)];
            s.h2[sW][b1][u1] = lstm_act(vi.x + vi.y, vf.x + vf.y,
                                        vg.x + vg.y, vo.x + vo.y, cc);
        }
        __syncthreads();
    }
    // final output (step TT-1) from h2[(TT-1)&1]
    if (svc) {
        const int b = wr - 204;
        float a0 = 0.f, a1 = 0.f, a2 = 0.f, a3 = 0.f;
        const float* h2p = &s.h2[(TT - 1) & 1][b][0];
        #pragma unroll
        for (int p = 0; p < 13; p++) {
            float4 w = *(const float4*)&s.WL[4 * p];
            float4 h = *(const float4*)&h2p[4 * p];
            a0 = fmaf(w.x, h.x, a0);  a1 = fmaf(w.y, h.y, a1);
            a2 = fmaf(w.z, h.z, a2);  a3 = fmaf(w.w, h.w, a3);
        }
        out[(size_t)(bb0 + b) * TT + (TT - 1)] = (a0 + a1) + (a2 + a3) + s.blin;
    }
    __syncthreads();   // ring STGs + OUTB all visible block-wide

    // --------------------- ring -> out pass (t = 0..T-1) ---------------------
    for (int idx = j; idx < T * NB; idx += NTH) {
        const int t = idx >> 2;
        const int b = idx & 3;
        const float* hp = &g_ring[blk][t][b][0];
        float a0 = 0.f, a1 = 0.f, a2 = 0.f, a3 = 0.f;
        #pragma unroll
        for (int p = 0; p < 13; p++) {
            float4 w = *(const float4*)&s.WL[4 * p];
            float4 h = *(const float4*)&hp[4 * p];
            a0 = fmaf(w.x, h.x, a0);  a1 = fmaf(w.y, h.y, a1);
            a2 = fmaf(w.z, h.z, a2);  a3 = fmaf(w.w, h.w, a3);
        }
        out[(size_t)(bb0 + b) * TT + t] = (a0 + a1) + (a2 + a3) + s.blin;
    }
}

extern "C" void kernel_launch(void* const* d_in, const int* in_sizes, int n_in,
                              void* d_out, int out_size)
{
    const float* input = (const float*)d_in[0];
    const float* Wih1  = (const float*)d_in[1];
    const float* Whh1  = (const float*)d_in[2];
    const float* bih1  = (const float*)d_in[3];
    const float* bhh1  = (const float*)d_in[4];
    const float* Wih2  = (const float*)d_in[5];
    const float* Whh2  = (const float*)d_in[6];
    const float* bih2  = (const float*)d_in[7];
    const float* bhh2  = (const float*)d_in[8];
    const float* Wlin  = (const float*)d_in[9];
    const float* blin  = (const float*)d_in[10];
    float* out = (float*)d_out;

    lstm_ring_kernel<<<NBLK, NTH>>>(
        input, Wih1, Whh1, bih1, bhh1, Wih2, Whh2, bih2, bhh2, Wlin, blin, out);
}